// round 12
// baseline (speedup 1.0000x reference)
#include <cuda_runtime.h>
#include <cuda_bf16.h>
#include <cstdint>
#include <cstddef>

#define D_MODEL 512
#define NHEAD   8
#define DH      64
#define BATCH   2
#define SEQ     2048
#define NTOK    (BATCH*SEQ)   // 4096
#define NBH     (BATCH*NHEAD) // 16
#define N1      (NTOK*D_MODEL)     // 2,097,152
#define N2      (D_MODEL*D_MODEL)  // 262,144

static const int       OUT_ELEMS  = N1;
static const long long ATTN_ELEMS = (long long)NBH*SEQ*SEQ;

// ---------------- device scratch (allocation-free rule) ----------------
__device__ __align__(16) __nv_bfloat16 g_INh[3*N1], g_INl[3*N1];
__device__ __align__(16) __nv_bfloat16 g_Wh[4*N2],  g_Wl[4*N2];
__device__ __align__(16) __nv_bfloat16 g_Qh[NBH*SEQ*DH], g_Ql[NBH*SEQ*DH];
__device__ __align__(16) __nv_bfloat16 g_Kh[NBH*SEQ*DH], g_Kl[NBH*SEQ*DH];
__device__ __align__(16) __nv_bfloat16 g_Vth[NBH*DH*SEQ], g_Vtl[NBH*DH*SEQ];
__device__ __align__(16) __nv_bfloat16 g_Ah[(size_t)NBH*SEQ*SEQ], g_Al[(size_t)NBH*SEQ*SEQ]; // exp hi/lo
__device__ __align__(16) __nv_bfloat16 g_Xh[N1], g_Xl[N1];
__device__ __align__(16) float         g_rowsum[NBH*SEQ];
__device__ __align__(16) float         g_attn_fallback[(size_t)NBH*SEQ*SEQ];

// ---------------- helpers ----------------
__device__ __forceinline__ uint32_t smem_u32(const void* p) {
    uint32_t a;
    asm("{ .reg .u64 t; cvta.to.shared.u64 t, %1; cvt.u32.u64 %0, t; }" : "=r"(a) : "l"(p));
    return a;
}
__device__ __forceinline__ void bf16_split(float v, __nv_bfloat16& hi, __nv_bfloat16& lo) {
    hi = __float2bfloat16(v);
    lo = __float2bfloat16(v - __bfloat162float(hi));
}
__device__ __forceinline__ uint32_t pack2(__nv_bfloat16 a, __nv_bfloat16 b) {
    return (uint32_t)__bfloat16_as_ushort(a) | ((uint32_t)__bfloat16_as_ushort(b) << 16);
}
__device__ __forceinline__ void mma_bf16(float d[4], const uint32_t a[4], const uint32_t b[2]) {
    asm volatile(
        "mma.sync.aligned.m16n8k16.row.col.f32.bf16.bf16.f32 "
        "{%0,%1,%2,%3}, {%4,%5,%6,%7}, {%8,%9}, {%0,%1,%2,%3};\n"
        : "+f"(d[0]), "+f"(d[1]), "+f"(d[2]), "+f"(d[3])
        : "r"(a[0]), "r"(a[1]), "r"(a[2]), "r"(a[3]), "r"(b[0]), "r"(b[1]));
}
__device__ __forceinline__ void ldsm_x4(uint32_t& r0, uint32_t& r1, uint32_t& r2, uint32_t& r3,
                                        uint32_t addr) {
    asm volatile("ldmatrix.sync.aligned.m8n8.x4.shared.b16 {%0,%1,%2,%3}, [%4];"
        : "=r"(r0), "=r"(r1), "=r"(r2), "=r"(r3) : "r"(addr));
}

#define TSTRIDE_B 144
#define TILE_BYTES (128*TSTRIDE_B)    // 18432
#define BTILE64    (64*TSTRIDE_B)     // 9216

#define CP_COMMIT() asm volatile("cp.async.commit_group;" ::: "memory")

__device__ __forceinline__ void cp_tile128(char* dst, const __nv_bfloat16* src, int ld, int tid) {
    const int row = tid >> 3, c = tid & 7;
#pragma unroll
    for (int t = 0; t < 4; t++) {
        uint32_t d = smem_u32(dst + (row + t*32)*TSTRIDE_B + c*16);
        const void* g = src + (size_t)(row + t*32)*ld + c*8;
        asm volatile("cp.async.cg.shared.global [%0], [%1], 16;" :: "r"(d), "l"(g) : "memory");
    }
}
__device__ __forceinline__ void cp_tile64(char* dst, const __nv_bfloat16* src, int ld, int tid) {
    const int row = tid >> 3, c = tid & 7;
#pragma unroll
    for (int t = 0; t < 2; t++) {
        uint32_t d = smem_u32(dst + (row + t*32)*TSTRIDE_B + c*16);
        const void* g = src + (size_t)(row + t*32)*ld + c*8;
        asm volatile("cp.async.cg.shared.global [%0], [%1], 16;" :: "r"(d), "l"(g) : "memory");
    }
}

// ---------------------------------------------------------------------------
// 3-pass (hh + h*lo + lo*h) HMMA with ldmatrix fragment loads.
// ---------------------------------------------------------------------------
template<int NT>
__device__ __forceinline__ void hmma_3pass(
    const char* A0c, const char* A1c, const char* B0c, const char* B1c,
    int i0w, int j0w, int gid, int tig, float acc[2][NT][4])
{
    const int lane = (threadIdx.x & 31);
    const uint32_t aoff = (uint32_t)(((lane & 7) + ((lane >> 3) & 1)*8)*TSTRIDE_B + (lane >> 4)*16);
    const uint32_t boff = (uint32_t)(((lane & 7) + ((lane >> 4) & 1)*8)*TSTRIDE_B + ((lane >> 3) & 1)*16);
    const uint32_t A0 = smem_u32(A0c) + i0w*TSTRIDE_B + aoff;
    const uint32_t A1 = smem_u32(A1c) + i0w*TSTRIDE_B + aoff;
    const uint32_t B0 = smem_u32(B0c) + j0w*TSTRIDE_B + boff;
    const uint32_t B1 = smem_u32(B1c) + j0w*TSTRIDE_B + boff;

#pragma unroll
    for (int pass = 0; pass < 3; pass++) {
        const uint32_t A = (pass == 2) ? A1 : A0;
        const uint32_t B = (pass == 1) ? B1 : B0;
#pragma unroll
        for (int ks = 0; ks < 4; ks++) {
            uint32_t a[2][4];
#pragma unroll
            for (int mt = 0; mt < 2; mt++)
                ldsm_x4(a[mt][0], a[mt][1], a[mt][2], a[mt][3],
                        A + mt*16*TSTRIDE_B + ks*32);
#pragma unroll
            for (int p = 0; p < NT/2; p++) {
                uint32_t b0, b1, b2, b3;
                ldsm_x4(b0, b1, b2, b3, B + p*16*TSTRIDE_B + ks*32);
                uint32_t bbA[2] = { b0, b1 };
                uint32_t bbB[2] = { b2, b3 };
                mma_bf16(acc[0][2*p+0], a[0], bbA);
                mma_bf16(acc[1][2*p+0], a[1], bbA);
                mma_bf16(acc[0][2*p+1], a[0], bbB);
                mma_bf16(acc[1][2*p+1], a[1], bbB);
            }
        }
    }
}

// ---------------------------------------------------------------------------
// Split kernel
// ---------------------------------------------------------------------------
__global__ void __launch_bounds__(256)
split_kernel(const float* __restrict__ q, const float* __restrict__ k, const float* __restrict__ v,
             const float* __restrict__ Wq, const float* __restrict__ Wk,
             const float* __restrict__ Wv, const float* __restrict__ Wo)
{
    const int which = blockIdx.y;
    const float* src; __nv_bfloat16* dh; __nv_bfloat16* dl; int count;
    if (which < 3) {
        src = (which == 0) ? q : (which == 1) ? k : v;
        dh = g_INh + (size_t)which*N1; dl = g_INl + (size_t)which*N1; count = N1/4;
    } else {
        const int w = which - 3;
        src = (w == 0) ? Wq : (w == 1) ? Wk : (w == 2) ? Wv : Wo;
        dh = g_Wh + (size_t)w*N2; dl = g_Wl + (size_t)w*N2; count = N2/4;
    }
    for (int i = blockIdx.x*blockDim.x + threadIdx.x; i < count; i += gridDim.x*blockDim.x) {
        float4 x = reinterpret_cast<const float4*>(src)[i];
        __nv_bfloat16 h0,l0,h1,l1,h2,l2,h3,l3;
        bf16_split(x.x,h0,l0); bf16_split(x.y,h1,l1);
        bf16_split(x.z,h2,l2); bf16_split(x.w,h3,l3);
        uint2 ph, pl;
        ph.x = pack2(h0,h1); ph.y = pack2(h2,h3);
        pl.x = pack2(l0,l1); pl.y = pack2(l2,l3);
        reinterpret_cast<uint2*>(dh)[i] = ph;
        reinterpret_cast<uint2*>(dl)[i] = pl;
    }
}

// ---------------------------------------------------------------------------
// QKV projection (unchanged)
// ---------------------------------------------------------------------------
#define PROJ_SMEM (8*TILE_BYTES)   // 147456
__global__ void __launch_bounds__(256)
qkv_proj_kernel(const float* __restrict__ bq, const float* __restrict__ bk,
                const float* __restrict__ bv)
{
    extern __shared__ char smem[];
    const int tid = threadIdx.x, wid = tid >> 5, lane = tid & 31;
    const int gid = lane >> 2, tig = lane & 3;
    const int z = blockIdx.z;
    const int m0 = blockIdx.y*128, n0 = blockIdx.x*128;
    const int i0w = (wid & 3)*32, j0w = (wid >> 2)*64;

    const __nv_bfloat16* Ah = g_INh + (size_t)z*N1 + (size_t)m0*D_MODEL;
    const __nv_bfloat16* Al = g_INl + (size_t)z*N1 + (size_t)m0*D_MODEL;
    const __nv_bfloat16* Bh = g_Wh  + (size_t)z*N2 + (size_t)n0*D_MODEL;
    const __nv_bfloat16* Bl = g_Wl  + (size_t)z*N2 + (size_t)n0*D_MODEL;
    const float* bias = (z == 0) ? bq : (z == 1) ? bk : bv;

    float acc[2][8][4];
#pragma unroll
    for (int mt = 0; mt < 2; mt++)
#pragma unroll
        for (int nt = 0; nt < 8; nt++)
#pragma unroll
            for (int q = 0; q < 4; q++) acc[mt][nt][q] = 0.f;

    {
        char* buf = smem;
        cp_tile128(buf,                Ah, D_MODEL, tid);
        cp_tile128(buf +   TILE_BYTES, Al, D_MODEL, tid);
        cp_tile128(buf + 2*TILE_BYTES, Bh, D_MODEL, tid);
        cp_tile128(buf + 3*TILE_BYTES, Bl, D_MODEL, tid);
        CP_COMMIT();
    }
    for (int ch = 0; ch < 8; ch++) {
        if (ch < 7) {
            char* buf = smem + ((ch+1)&1)*(4*TILE_BYTES);
            const int k0 = (ch+1)*64;
            cp_tile128(buf,                Ah + k0, D_MODEL, tid);
            cp_tile128(buf +   TILE_BYTES, Al + k0, D_MODEL, tid);
            cp_tile128(buf + 2*TILE_BYTES, Bh + k0, D_MODEL, tid);
            cp_tile128(buf + 3*TILE_BYTES, Bl + k0, D_MODEL, tid);
            CP_COMMIT();
            asm volatile("cp.async.wait_group 1;" ::: "memory");
        } else {
            asm volatile("cp.async.wait_group 0;" ::: "memory");
        }
        __syncthreads();
        char* buf = smem + (ch&1)*(4*TILE_BYTES);
        hmma_3pass<8>(buf, buf + TILE_BYTES, buf + 2*TILE_BYTES, buf + 3*TILE_BYTES,
                      i0w, j0w, gid, tig, acc);
        __syncthreads();
    }

#pragma unroll
    for (int nt = 0; nt < 8; nt++) {
        const int col = n0 + j0w + nt*8 + tig*2;
        const int h = col >> 6, d = col & 63;
        const float b0v = bias[col], b1v = bias[col+1];
#pragma unroll
        for (int mt = 0; mt < 2; mt++) {
#pragma unroll
            for (int half = 0; half < 2; half++) {
                const int token = m0 + i0w + mt*16 + gid + half*8;
                const int b = token >> 11, s = token & 2047;
                float v0 = acc[mt][nt][half*2+0] + b0v;
                float v1 = acc[mt][nt][half*2+1] + b1v;
                __nv_bfloat16 h0,l0,h1,l1;
                bf16_split(v0,h0,l0); bf16_split(v1,h1,l1);
                if (z == 0) {
                    size_t o = ((size_t)(b*NHEAD + h)*SEQ + s)*DH + d;
                    *reinterpret_cast<uint32_t*>(g_Qh + o) = pack2(h0,h1);
                    *reinterpret_cast<uint32_t*>(g_Ql + o) = pack2(l0,l1);
                } else if (z == 1) {
                    size_t o = ((size_t)(b*NHEAD + h)*SEQ + s)*DH + d;
                    *reinterpret_cast<uint32_t*>(g_Kh + o) = pack2(h0,h1);
                    *reinterpret_cast<uint32_t*>(g_Kl + o) = pack2(l0,l1);
                } else {
                    size_t o0 = ((size_t)(b*NHEAD + h)*DH + d)*SEQ + s;
                    g_Vth[o0] = h0; g_Vtl[o0] = l0;
                    g_Vth[o0 + SEQ] = h1; g_Vtl[o0 + SEQ] = l1;
                }
            }
        }
    }
}

// ---------------------------------------------------------------------------
// Output projection (unchanged)
// ---------------------------------------------------------------------------
__global__ void __launch_bounds__(256)
oproj_kernel(const float* __restrict__ bo, float* __restrict__ out)
{
    extern __shared__ char smem[];
    const int tid = threadIdx.x, wid = tid >> 5, lane = tid & 31;
    const int gid = lane >> 2, tig = lane & 3;
    const int m0 = blockIdx.y*128, n0 = blockIdx.x*128;
    const int i0w = (wid & 3)*32, j0w = (wid >> 2)*64;

    const __nv_bfloat16* Ah = g_Xh + (size_t)m0*D_MODEL;
    const __nv_bfloat16* Al = g_Xl + (size_t)m0*D_MODEL;
    const __nv_bfloat16* Bh = g_Wh + (size_t)3*N2 + (size_t)n0*D_MODEL;
    const __nv_bfloat16* Bl = g_Wl + (size_t)3*N2 + (size_t)n0*D_MODEL;

    float acc[2][8][4];
#pragma unroll
    for (int mt = 0; mt < 2; mt++)
#pragma unroll
        for (int nt = 0; nt < 8; nt++)
#pragma unroll
            for (int q = 0; q < 4; q++) acc[mt][nt][q] = 0.f;

    {
        char* buf = smem;
        cp_tile128(buf,                Ah, D_MODEL, tid);
        cp_tile128(buf +   TILE_BYTES, Al, D_MODEL, tid);
        cp_tile128(buf + 2*TILE_BYTES, Bh, D_MODEL, tid);
        cp_tile128(buf + 3*TILE_BYTES, Bl, D_MODEL, tid);
        CP_COMMIT();
    }
    for (int ch = 0; ch < 8; ch++) {
        if (ch < 7) {
            char* buf = smem + ((ch+1)&1)*(4*TILE_BYTES);
            const int k0 = (ch+1)*64;
            cp_tile128(buf,                Ah + k0, D_MODEL, tid);
            cp_tile128(buf +   TILE_BYTES, Al + k0, D_MODEL, tid);
            cp_tile128(buf + 2*TILE_BYTES, Bh + k0, D_MODEL, tid);
            cp_tile128(buf + 3*TILE_BYTES, Bl + k0, D_MODEL, tid);
            CP_COMMIT();
            asm volatile("cp.async.wait_group 1;" ::: "memory");
        } else {
            asm volatile("cp.async.wait_group 0;" ::: "memory");
        }
        __syncthreads();
        char* buf = smem + (ch&1)*(4*TILE_BYTES);
        hmma_3pass<8>(buf, buf + TILE_BYTES, buf + 2*TILE_BYTES, buf + 3*TILE_BYTES,
                      i0w, j0w, gid, tig, acc);
        __syncthreads();
    }

#pragma unroll
    for (int nt = 0; nt < 8; nt++) {
        const int col = n0 + j0w + nt*8 + tig*2;
        const float b0v = bo[col], b1v = bo[col+1];
#pragma unroll
        for (int mt = 0; mt < 2; mt++) {
#pragma unroll
            for (int half = 0; half < 2; half++) {
                const int row = m0 + i0w + mt*16 + gid + half*8;
                float2 o;
                o.x = acc[mt][nt][half*2+0] + b0v;
                o.y = acc[mt][nt][half*2+1] + b1v;
                *reinterpret_cast<float2*>(out + (size_t)row*D_MODEL + col) = o;
            }
        }
    }
}

// ---------------------------------------------------------------------------
// Streaming score kernel: CTA = 128 q-rows x full 2048 cols, one bh.
// Q resident; K double-buffered (16 chunks of 128 cols). Per chunk:
// HMMA -> exp -> stage bf16 hi/lo in smem -> coalesced drain (overlaps next
// K prefetch). Exact per-CTA row sums -> plain store (no atomics/zeroing).
// smem: Q(2x18432) + K dbuf(2x36864) + staging(2x34816) + rowsum(512)
// ---------------------------------------------------------------------------
#define ESTRIDE 272
#define ETILE   (128*ESTRIDE)          // 34816
#define SS_K0   (2*TILE_BYTES)         // 36864
#define SS_E    (6*TILE_BYTES)         // 110592
#define SS_ROW  (SS_E + 2*ETILE)       // 180224
#define SCORE_SMEM (SS_ROW + 512)      // 180736
__global__ void __launch_bounds__(256)
score_stream_kernel(const int* __restrict__ mask)
{
    extern __shared__ char smem[];
    char* sQ0 = smem;
    char* sQ1 = smem + TILE_BYTES;
    char* sE0 = smem + SS_E;
    char* sE1 = smem + SS_E + ETILE;
    float* srow = reinterpret_cast<float*>(smem + SS_ROW);

    const int tid = threadIdx.x, wid = tid >> 5, lane = tid & 31;
    const int gid = lane >> 2, tig = lane & 3;
    const int bh = blockIdx.y, b = bh >> 3;
    const int m0 = blockIdx.x * 128;
    const int i0w = (wid & 3)*32, j0w = (wid >> 2)*64;

    const __nv_bfloat16* Kh = g_Kh + (size_t)bh*SEQ*DH;
    const __nv_bfloat16* Kl = g_Kl + (size_t)bh*SEQ*DH;

    if (tid < 128) srow[tid] = 0.f;

    // group 0: Q + K(0); group 1: K(1)
    cp_tile128(sQ0, g_Qh + ((size_t)bh*SEQ + m0)*DH, DH, tid);
    cp_tile128(sQ1, g_Ql + ((size_t)bh*SEQ + m0)*DH, DH, tid);
    {
        char* kb = smem + SS_K0;
        cp_tile128(kb,              Kh, DH, tid);
        cp_tile128(kb + TILE_BYTES, Kl, DH, tid);
        CP_COMMIT();
        kb = smem + SS_K0 + 2*TILE_BYTES;
        cp_tile128(kb,              Kh + (size_t)128*DH, DH, tid);
        cp_tile128(kb + TILE_BYTES, Kl + (size_t)128*DH, DH, tid);
        CP_COMMIT();
    }

    float rsum[2][2] = { {0.f, 0.f}, {0.f, 0.f} };

    for (int ch = 0; ch < 16; ch++) {
        if (ch < 14) asm volatile("cp.async.wait_group 1;" ::: "memory");
        else         asm volatile("cp.async.wait_group 0;" ::: "memory");
        __syncthreads();   // K(ch) ready; previous drain complete

        char* kb = smem + SS_K0 + (ch&1)*(2*TILE_BYTES);

        float acc[2][8][4];
#pragma unroll
        for (int mt = 0; mt < 2; mt++)
#pragma unroll
            for (int nt = 0; nt < 8; nt++)
#pragma unroll
                for (int q = 0; q < 4; q++) acc[mt][nt][q] = 0.f;

        hmma_3pass<8>(sQ0, sQ1, kb, kb + TILE_BYTES, i0w, j0w, gid, tig, acc);
        __syncthreads();   // hmma done; kb reusable

        if (ch < 14) {
            char* nkb = smem + SS_K0 + (ch&1)*(2*TILE_BYTES);
            const int r0 = (ch+2)*128;
            cp_tile128(nkb,              Kh + (size_t)r0*DH, DH, tid);
            cp_tile128(nkb + TILE_BYTES, Kl + (size_t)r0*DH, DH, tid);
            CP_COMMIT();
        }

        // epilogue: exp, rowsum accumulate, split+stage
#pragma unroll
        for (int nt = 0; nt < 8; nt++) {
            const int colw = (j0w >> 1) + nt*4 + tig;
            const int col = ch*128 + j0w + nt*8 + tig*2;
            const int mv0 = __ldg(mask + b*SEQ + col);
            const int mv1 = __ldg(mask + b*SEQ + col + 1);
#pragma unroll
            for (int mt = 0; mt < 2; mt++) {
#pragma unroll
                for (int half = 0; half < 2; half++) {
                    const int rl = i0w + mt*16 + gid + half*8;
                    float e0 = __expf(acc[mt][nt][half*2+0] * 0.125f);
                    float e1 = __expf(acc[mt][nt][half*2+1] * 0.125f);
                    if (mv0 == 0) e0 = 0.f;
                    if (mv1 == 0) e1 = 0.f;
                    rsum[mt][half] += e0 + e1;
                    __nv_bfloat16 h0,l0,h1,l1;
                    bf16_split(e0,h0,l0); bf16_split(e1,h1,l1);
                    *reinterpret_cast<uint32_t*>(sE0 + rl*ESTRIDE + colw*4) = pack2(h0,h1);
                    *reinterpret_cast<uint32_t*>(sE1 + rl*ESTRIDE + colw*4) = pack2(l0,l1);
                }
            }
        }
        __syncthreads();   // staging complete

        // coalesced drain: 16 threads per 256B row, 16 rows per pass
        {
            const int rsub = tid >> 4;
            const int cw   = tid & 15;
#pragma unroll
            for (int it = 0; it < 8; it++) {
                const int rl = it*16 + rsub;
                uint4 vh = *reinterpret_cast<uint4*>(sE0 + rl*ESTRIDE + cw*16);
                uint4 vl = *reinterpret_cast<uint4*>(sE1 + rl*ESTRIDE + cw*16);
                size_t o = ((size_t)bh*SEQ + m0 + rl)*SEQ + ch*128 + cw*8;
                *reinterpret_cast<uint4*>(g_Ah + o) = vh;
                *reinterpret_cast<uint4*>(g_Al + o) = vl;
            }
        }
    }

    // exact row sums: lane-reduce (4 lanes/row), smem atomic across warps, store
#pragma unroll
    for (int mt = 0; mt < 2; mt++)
#pragma unroll
        for (int half = 0; half < 2; half++) {
            float s = rsum[mt][half];
            s += __shfl_xor_sync(0xffffffffu, s, 1);
            s += __shfl_xor_sync(0xffffffffu, s, 2);
            if (tig == 0) {
                const int rl = i0w + mt*16 + gid + half*8;
                atomicAdd(&srow[rl], s);
            }
        }
    __syncthreads();
    if (tid < 128) g_rowsum[bh*SEQ + m0 + tid] = srow[tid];
}

// ---------------------------------------------------------------------------
// Normalize kernel: attn[row][:] = (Eh+El) * inv(rowsum).
// ---------------------------------------------------------------------------
__global__ void __launch_bounds__(256)
normalize_kernel(float* attn_arg)
{
    float* attn = attn_arg ? attn_arg : g_attn_fallback;
    const size_t row = blockIdx.x;
    const float inv = 1.0f / g_rowsum[row];
    const int tid = threadIdx.x;
    const size_t off = row * (size_t)SEQ + tid*8;

    uint4 eh = *reinterpret_cast<const uint4*>(g_Ah + off);
    uint4 el = *reinterpret_cast<const uint4*>(g_Al + off);
    const uint32_t* hp = reinterpret_cast<const uint32_t*>(&eh);
    const uint32_t* lp = reinterpret_cast<const uint32_t*>(&el);

    float o[8];
#pragma unroll
    for (int q = 0; q < 4; q++) {
        __nv_bfloat162 h2 = *reinterpret_cast<const __nv_bfloat162*>(hp + q);
        __nv_bfloat162 l2 = *reinterpret_cast<const __nv_bfloat162*>(lp + q);
        o[2*q+0] = (__bfloat162float(h2.x) + __bfloat162float(l2.x)) * inv;
        o[2*q+1] = (__bfloat162float(h2.y) + __bfloat162float(l2.y)) * inv;
    }
    float* dst = attn + off;
    *reinterpret_cast<float4*>(dst)     = make_float4(o[0], o[1], o[2], o[3]);
    *reinterpret_cast<float4*>(dst + 4) = make_float4(o[4], o[5], o[6], o[7]);
}

// ---------------------------------------------------------------------------
// PV kernel: A = Eh/El (unnormalized exp), scale by inv(rowsum) at epilogue.
// ---------------------------------------------------------------------------
#define PVBUF   (2*TILE_BYTES + 2*BTILE64)   // 55296
#define PV_SMEM (2*PVBUF)                     // 110592
__global__ void __launch_bounds__(256)
pv_kernel()
{
    extern __shared__ char smem[];
    const int tid = threadIdx.x, wid = tid >> 5, lane = tid & 31;
    const int gid = lane >> 2, tig = lane & 3;
    const int bh = blockIdx.y, b = bh >> 3, h = bh & 7;
    const int m0 = blockIdx.x * 128;
    const int i0w = (wid & 3)*32, d0w = (wid >> 2)*32;

    const __nv_bfloat16* Ah = g_Ah + ((size_t)bh*SEQ + m0)*SEQ;
    const __nv_bfloat16* Al = g_Al + ((size_t)bh*SEQ + m0)*SEQ;
    const __nv_bfloat16* Bh = g_Vth + (size_t)bh*DH*SEQ;
    const __nv_bfloat16* Bl = g_Vtl + (size_t)bh*DH*SEQ;

    float acc[2][4][4];
#pragma unroll
    for (int mt = 0; mt < 2; mt++)
#pragma unroll
        for (int nt = 0; nt < 4; nt++)
#pragma unroll
            for (int q = 0; q < 4; q++) acc[mt][nt][q] = 0.f;

    {
        char* buf = smem;
        cp_tile128(buf,                         Ah, SEQ, tid);
        cp_tile128(buf + TILE_BYTES,            Al, SEQ, tid);
        cp_tile64 (buf + 2*TILE_BYTES,           Bh, SEQ, tid);
        cp_tile64 (buf + 2*TILE_BYTES + BTILE64, Bl, SEQ, tid);
        CP_COMMIT();
    }
    for (int ch = 0; ch < 32; ch++) {
        if (ch < 31) {
            char* buf = smem + ((ch+1)&1)*PVBUF;
            const int j0 = (ch+1)*64;
            cp_tile128(buf,                         Ah + j0, SEQ, tid);
            cp_tile128(buf + TILE_BYTES,            Al + j0, SEQ, tid);
            cp_tile64 (buf + 2*TILE_BYTES,           Bh + j0, SEQ, tid);
            cp_tile64 (buf + 2*TILE_BYTES + BTILE64, Bl + j0, SEQ, tid);
            CP_COMMIT();
            asm volatile("cp.async.wait_group 1;" ::: "memory");
        } else {
            asm volatile("cp.async.wait_group 0;" ::: "memory");
        }
        __syncthreads();
        char* buf = smem + (ch&1)*PVBUF;
        hmma_3pass<4>(buf, buf + TILE_BYTES, buf + 2*TILE_BYTES, buf + 2*TILE_BYTES + BTILE64,
                      i0w, d0w, gid, tig, acc);
        __syncthreads();
    }

    float invr[2][2];
#pragma unroll
    for (int mt = 0; mt < 2; mt++)
#pragma unroll
        for (int half = 0; half < 2; half++) {
            const int row = m0 + i0w + mt*16 + gid + half*8;
            invr[mt][half] = 1.0f / g_rowsum[bh*SEQ + row];
        }

#pragma unroll
    for (int nt = 0; nt < 4; nt++) {
        const int d = d0w + nt*8 + tig*2;
#pragma unroll
        for (int mt = 0; mt < 2; mt++) {
#pragma unroll
            for (int half = 0; half < 2; half++) {
                const int row = m0 + i0w + mt*16 + gid + half*8;
                float v0 = acc[mt][nt][half*2+0] * invr[mt][half];
                float v1 = acc[mt][nt][half*2+1] * invr[mt][half];
                __nv_bfloat16 h0,l0,h1,l1;
                bf16_split(v0,h0,l0); bf16_split(v1,h1,l1);
                size_t o = ((size_t)(b*SEQ + row))*D_MODEL + h*DH + d;
                *reinterpret_cast<uint32_t*>(g_Xh + o) = pack2(h0,h1);
                *reinterpret_cast<uint32_t*>(g_Xl + o) = pack2(l0,l1);
            }
        }
    }
}

// ---------------------------------------------------------------------------
extern "C" void kernel_launch(void* const* d_in, const int* in_sizes, int n_in,
                              void* d_out, int out_size)
{
    const float* query = (const float*)d_in[0];
    const float* key   = (const float*)d_in[1];
    const float* value = (const float*)d_in[2];
    const int*   mask  = (const int*)  d_in[3];
    const float* Wq    = (const float*)d_in[4];
    const float* bq    = (const float*)d_in[5];
    const float* Wk    = (const float*)d_in[6];
    const float* bk    = (const float*)d_in[7];
    const float* Wv    = (const float*)d_in[8];
    const float* bv    = (const float*)d_in[9];
    const float* Wo    = (const float*)d_in[10];
    const float* bo    = (const float*)d_in[11];

    float* out = (float*)d_out;
    float* attn_arg = ((long long)out_size >= (long long)OUT_ELEMS + ATTN_ELEMS)
                      ? (out + OUT_ELEMS) : nullptr;

    cudaFuncSetAttribute(qkv_proj_kernel,     cudaFuncAttributeMaxDynamicSharedMemorySize, PROJ_SMEM);
    cudaFuncSetAttribute(oproj_kernel,        cudaFuncAttributeMaxDynamicSharedMemorySize, PROJ_SMEM);
    cudaFuncSetAttribute(score_stream_kernel, cudaFuncAttributeMaxDynamicSharedMemorySize, SCORE_SMEM);
    cudaFuncSetAttribute(pv_kernel,           cudaFuncAttributeMaxDynamicSharedMemorySize, PV_SMEM);

    dim3 blk(256);
    split_kernel       <<<dim3(256, 7), blk>>>(query, key, value, Wq, Wk, Wv, Wo);
    qkv_proj_kernel    <<<dim3(4, 32, 3), blk, PROJ_SMEM>>>(bq, bk, bv);
    score_stream_kernel<<<dim3(16, 16), blk, SCORE_SMEM>>>(mask);
    pv_kernel          <<<dim3(16, 16), blk, PV_SMEM>>>();
    normalize_kernel   <<<dim3(NBH*SEQ), blk>>>(attn_arg);
    oproj_kernel       <<<dim3(4, 32), blk, PROJ_SMEM>>>(bo, out);
}

// round 13
// speedup vs baseline: 1.0651x; 1.0651x over previous
#include <cuda_runtime.h>
#include <cuda_bf16.h>
#include <cstdint>
#include <cstddef>

#define D_MODEL 512
#define NHEAD   8
#define DH      64
#define BATCH   2
#define SEQ     2048
#define NTOK    (BATCH*SEQ)   // 4096
#define NBH     (BATCH*NHEAD) // 16
#define N1      (NTOK*D_MODEL)     // 2,097,152
#define N2      (D_MODEL*D_MODEL)  // 262,144

static const int       OUT_ELEMS  = N1;
static const long long ATTN_ELEMS = (long long)NBH*SEQ*SEQ;

// ---------------- device scratch (allocation-free rule) ----------------
__device__ __align__(16) __nv_bfloat16 g_INh[3*N1], g_INl[3*N1];
__device__ __align__(16) __nv_bfloat16 g_Wh[4*N2],  g_Wl[4*N2];
__device__ __align__(16) __nv_bfloat16 g_Qh[NBH*SEQ*DH], g_Ql[NBH*SEQ*DH];
__device__ __align__(16) __nv_bfloat16 g_Kh[NBH*SEQ*DH], g_Kl[NBH*SEQ*DH];
__device__ __align__(16) __nv_bfloat16 g_Vth[NBH*DH*SEQ], g_Vtl[NBH*DH*SEQ];
__device__ __align__(16) __nv_bfloat16 g_Ah[(size_t)NBH*SEQ*SEQ], g_Al[(size_t)NBH*SEQ*SEQ];
__device__ __align__(16) __nv_bfloat16 g_Xh[N1], g_Xl[N1];
__device__ __align__(16) float         g_attn_fallback[(size_t)NBH*SEQ*SEQ];

// ---------------- helpers ----------------
__device__ __forceinline__ uint32_t smem_u32(const void* p) {
    uint32_t a;
    asm("{ .reg .u64 t; cvta.to.shared.u64 t, %1; cvt.u32.u64 %0, t; }" : "=r"(a) : "l"(p));
    return a;
}
__device__ __forceinline__ void bf16_split(float v, __nv_bfloat16& hi, __nv_bfloat16& lo) {
    hi = __float2bfloat16(v);
    lo = __float2bfloat16(v - __bfloat162float(hi));
}
__device__ __forceinline__ uint32_t pack2(__nv_bfloat16 a, __nv_bfloat16 b) {
    return (uint32_t)__bfloat16_as_ushort(a) | ((uint32_t)__bfloat16_as_ushort(b) << 16);
}
__device__ __forceinline__ void mma_bf16(float d[4], const uint32_t a[4], const uint32_t b[2]) {
    asm volatile(
        "mma.sync.aligned.m16n8k16.row.col.f32.bf16.bf16.f32 "
        "{%0,%1,%2,%3}, {%4,%5,%6,%7}, {%8,%9}, {%0,%1,%2,%3};\n"
        : "+f"(d[0]), "+f"(d[1]), "+f"(d[2]), "+f"(d[3])
        : "r"(a[0]), "r"(a[1]), "r"(a[2]), "r"(a[3]), "r"(b[0]), "r"(b[1]));
}
__device__ __forceinline__ void ldsm_x4(uint32_t& r0, uint32_t& r1, uint32_t& r2, uint32_t& r3,
                                        uint32_t addr) {
    asm volatile("ldmatrix.sync.aligned.m8n8.x4.shared.b16 {%0,%1,%2,%3}, [%4];"
        : "=r"(r0), "=r"(r1), "=r"(r2), "=r"(r3) : "r"(addr));
}

#define TSTRIDE_B 144
#define TILE_BYTES (128*TSTRIDE_B)    // 18432
#define BTILE64    (64*TSTRIDE_B)     // 9216

#define CP_COMMIT() asm volatile("cp.async.commit_group;" ::: "memory")

__device__ __forceinline__ void cp_tile128(char* dst, const __nv_bfloat16* src, int ld, int tid) {
    const int row = tid >> 3, c = tid & 7;
#pragma unroll
    for (int t = 0; t < 4; t++) {
        uint32_t d = smem_u32(dst + (row + t*32)*TSTRIDE_B + c*16);
        const void* g = src + (size_t)(row + t*32)*ld + c*8;
        asm volatile("cp.async.cg.shared.global [%0], [%1], 16;" :: "r"(d), "l"(g) : "memory");
    }
}
__device__ __forceinline__ void cp_tile64(char* dst, const __nv_bfloat16* src, int ld, int tid) {
    const int row = tid >> 3, c = tid & 7;
#pragma unroll
    for (int t = 0; t < 2; t++) {
        uint32_t d = smem_u32(dst + (row + t*32)*TSTRIDE_B + c*16);
        const void* g = src + (size_t)(row + t*32)*ld + c*8;
        asm volatile("cp.async.cg.shared.global [%0], [%1], 16;" :: "r"(d), "l"(g) : "memory");
    }
}

// ---------------------------------------------------------------------------
// 3-pass (hh + h*lo + lo*h) HMMA with ldmatrix fragment loads.
// ---------------------------------------------------------------------------
template<int NT>
__device__ __forceinline__ void hmma_3pass(
    const char* A0c, const char* A1c, const char* B0c, const char* B1c,
    int i0w, int j0w, int gid, int tig, float acc[2][NT][4])
{
    const int lane = (threadIdx.x & 31);
    const uint32_t aoff = (uint32_t)(((lane & 7) + ((lane >> 3) & 1)*8)*TSTRIDE_B + (lane >> 4)*16);
    const uint32_t boff = (uint32_t)(((lane & 7) + ((lane >> 4) & 1)*8)*TSTRIDE_B + ((lane >> 3) & 1)*16);
    const uint32_t A0 = smem_u32(A0c) + i0w*TSTRIDE_B + aoff;
    const uint32_t A1 = smem_u32(A1c) + i0w*TSTRIDE_B + aoff;
    const uint32_t B0 = smem_u32(B0c) + j0w*TSTRIDE_B + boff;
    const uint32_t B1 = smem_u32(B1c) + j0w*TSTRIDE_B + boff;

#pragma unroll
    for (int pass = 0; pass < 3; pass++) {
        const uint32_t A = (pass == 2) ? A1 : A0;
        const uint32_t B = (pass == 1) ? B1 : B0;
#pragma unroll
        for (int ks = 0; ks < 4; ks++) {
            uint32_t a[2][4];
#pragma unroll
            for (int mt = 0; mt < 2; mt++)
                ldsm_x4(a[mt][0], a[mt][1], a[mt][2], a[mt][3],
                        A + mt*16*TSTRIDE_B + ks*32);
#pragma unroll
            for (int p = 0; p < NT/2; p++) {
                uint32_t b0, b1, b2, b3;
                ldsm_x4(b0, b1, b2, b3, B + p*16*TSTRIDE_B + ks*32);
                uint32_t bbA[2] = { b0, b1 };
                uint32_t bbB[2] = { b2, b3 };
                mma_bf16(acc[0][2*p+0], a[0], bbA);
                mma_bf16(acc[1][2*p+0], a[1], bbA);
                mma_bf16(acc[0][2*p+1], a[0], bbB);
                mma_bf16(acc[1][2*p+1], a[1], bbB);
            }
        }
    }
}

// ---------------------------------------------------------------------------
// Split kernel
// ---------------------------------------------------------------------------
__global__ void __launch_bounds__(256)
split_kernel(const float* __restrict__ q, const float* __restrict__ k, const float* __restrict__ v,
             const float* __restrict__ Wq, const float* __restrict__ Wk,
             const float* __restrict__ Wv, const float* __restrict__ Wo)
{
    const int which = blockIdx.y;
    const float* src; __nv_bfloat16* dh; __nv_bfloat16* dl; int count;
    if (which < 3) {
        src = (which == 0) ? q : (which == 1) ? k : v;
        dh = g_INh + (size_t)which*N1; dl = g_INl + (size_t)which*N1; count = N1/4;
    } else {
        const int w = which - 3;
        src = (w == 0) ? Wq : (w == 1) ? Wk : (w == 2) ? Wv : Wo;
        dh = g_Wh + (size_t)w*N2; dl = g_Wl + (size_t)w*N2; count = N2/4;
    }
    for (int i = blockIdx.x*blockDim.x + threadIdx.x; i < count; i += gridDim.x*blockDim.x) {
        float4 x = reinterpret_cast<const float4*>(src)[i];
        __nv_bfloat16 h0,l0,h1,l1,h2,l2,h3,l3;
        bf16_split(x.x,h0,l0); bf16_split(x.y,h1,l1);
        bf16_split(x.z,h2,l2); bf16_split(x.w,h3,l3);
        uint2 ph, pl;
        ph.x = pack2(h0,h1); ph.y = pack2(h2,h3);
        pl.x = pack2(l0,l1); pl.y = pack2(l2,l3);
        reinterpret_cast<uint2*>(dh)[i] = ph;
        reinterpret_cast<uint2*>(dl)[i] = pl;
    }
}

// ---------------------------------------------------------------------------
// QKV projection. z==2 (V) epilogue: stage transposed hi/lo tiles in smem,
// drain with coalesced 16B stores (V-transposed rows are SEQ-contiguous).
// ---------------------------------------------------------------------------
#define VSTRIDE 272                    // staging row stride (bytes), conflict-free
#define VTILE   (128*VSTRIDE)          // 34816
#define PROJ_SMEM (8*TILE_BYTES)       // 147456 >= 2*VTILE = 69632
__global__ void __launch_bounds__(256)
qkv_proj_kernel(const float* __restrict__ bq, const float* __restrict__ bk,
                const float* __restrict__ bv)
{
    extern __shared__ char smem[];
    const int tid = threadIdx.x, wid = tid >> 5, lane = tid & 31;
    const int gid = lane >> 2, tig = lane & 3;
    const int z = blockIdx.z;
    const int m0 = blockIdx.y*128, n0 = blockIdx.x*128;
    const int i0w = (wid & 3)*32, j0w = (wid >> 2)*64;

    const __nv_bfloat16* Ah = g_INh + (size_t)z*N1 + (size_t)m0*D_MODEL;
    const __nv_bfloat16* Al = g_INl + (size_t)z*N1 + (size_t)m0*D_MODEL;
    const __nv_bfloat16* Bh = g_Wh  + (size_t)z*N2 + (size_t)n0*D_MODEL;
    const __nv_bfloat16* Bl = g_Wl  + (size_t)z*N2 + (size_t)n0*D_MODEL;
    const float* bias = (z == 0) ? bq : (z == 1) ? bk : bv;

    float acc[2][8][4];
#pragma unroll
    for (int mt = 0; mt < 2; mt++)
#pragma unroll
        for (int nt = 0; nt < 8; nt++)
#pragma unroll
            for (int q = 0; q < 4; q++) acc[mt][nt][q] = 0.f;

    {
        char* buf = smem;
        cp_tile128(buf,                Ah, D_MODEL, tid);
        cp_tile128(buf +   TILE_BYTES, Al, D_MODEL, tid);
        cp_tile128(buf + 2*TILE_BYTES, Bh, D_MODEL, tid);
        cp_tile128(buf + 3*TILE_BYTES, Bl, D_MODEL, tid);
        CP_COMMIT();
    }
    for (int ch = 0; ch < 8; ch++) {
        if (ch < 7) {
            char* buf = smem + ((ch+1)&1)*(4*TILE_BYTES);
            const int k0 = (ch+1)*64;
            cp_tile128(buf,                Ah + k0, D_MODEL, tid);
            cp_tile128(buf +   TILE_BYTES, Al + k0, D_MODEL, tid);
            cp_tile128(buf + 2*TILE_BYTES, Bh + k0, D_MODEL, tid);
            cp_tile128(buf + 3*TILE_BYTES, Bl + k0, D_MODEL, tid);
            CP_COMMIT();
            asm volatile("cp.async.wait_group 1;" ::: "memory");
        } else {
            asm volatile("cp.async.wait_group 0;" ::: "memory");
        }
        __syncthreads();
        char* buf = smem + (ch&1)*(4*TILE_BYTES);
        hmma_3pass<8>(buf, buf + TILE_BYTES, buf + 2*TILE_BYTES, buf + 3*TILE_BYTES,
                      i0w, j0w, gid, tig, acc);
        __syncthreads();
    }

    if (z < 2) {
        // Q/K epilogue: head-sliced [bh][s][d], 4B packed stores
#pragma unroll
        for (int nt = 0; nt < 8; nt++) {
            const int col = n0 + j0w + nt*8 + tig*2;
            const int h = col >> 6, d = col & 63;
            const float b0v = bias[col], b1v = bias[col+1];
#pragma unroll
            for (int mt = 0; mt < 2; mt++) {
#pragma unroll
                for (int half = 0; half < 2; half++) {
                    const int token = m0 + i0w + mt*16 + gid + half*8;
                    const int b = token >> 11, s = token & 2047;
                    float v0 = acc[mt][nt][half*2+0] + b0v;
                    float v1 = acc[mt][nt][half*2+1] + b1v;
                    __nv_bfloat16 h0,l0,h1,l1;
                    bf16_split(v0,h0,l0); bf16_split(v1,h1,l1);
                    size_t o = ((size_t)(b*NHEAD + h)*SEQ + s)*DH + d;
                    if (z == 0) {
                        *reinterpret_cast<uint32_t*>(g_Qh + o) = pack2(h0,h1);
                        *reinterpret_cast<uint32_t*>(g_Ql + o) = pack2(l0,l1);
                    } else {
                        *reinterpret_cast<uint32_t*>(g_Kh + o) = pack2(h0,h1);
                        *reinterpret_cast<uint32_t*>(g_Kl + o) = pack2(l0,l1);
                    }
                }
            }
        }
    } else {
        // V epilogue: transpose-stage in smem, then coalesced drain.
        // Staging layout: [colLocal 0..127][tokenLocal 0..127] bf16, stride 272B.
        char* sVh = smem;            // buffer 0 region, free after mainloop
        char* sVl = smem + VTILE;
#pragma unroll
        for (int nt = 0; nt < 8; nt++) {
            const int colL = j0w + nt*8 + tig*2;
            const int col = n0 + colL;
            const float b0v = bias[col], b1v = bias[col+1];
#pragma unroll
            for (int mt = 0; mt < 2; mt++) {
#pragma unroll
                for (int half = 0; half < 2; half++) {
                    const int tok = i0w + mt*16 + gid + half*8;
                    float v0 = acc[mt][nt][half*2+0] + b0v;
                    float v1 = acc[mt][nt][half*2+1] + b1v;
                    __nv_bfloat16 h0,l0,h1,l1;
                    bf16_split(v0,h0,l0); bf16_split(v1,h1,l1);
                    *reinterpret_cast<__nv_bfloat16*>(sVh + colL*VSTRIDE + tok*2)     = h0;
                    *reinterpret_cast<__nv_bfloat16*>(sVh + (colL+1)*VSTRIDE + tok*2) = h1;
                    *reinterpret_cast<__nv_bfloat16*>(sVl + colL*VSTRIDE + tok*2)     = l0;
                    *reinterpret_cast<__nv_bfloat16*>(sVl + (colL+1)*VSTRIDE + tok*2) = l1;
                }
            }
        }
        __syncthreads();
        // drain: row = colLocal (128 rows x 256B); 16 threads x 16B per row
        const int b  = m0 >> 11, s0 = m0 & 2047;
        const int rsub = tid >> 4, cw = tid & 15;
#pragma unroll
        for (int it = 0; it < 8; it++) {
            const int rl = it*16 + rsub;          // colLocal
            const int col = n0 + rl;
            const int h = col >> 6, d = col & 63;
            uint4 vh = *reinterpret_cast<uint4*>(sVh + rl*VSTRIDE + cw*16);
            uint4 vl = *reinterpret_cast<uint4*>(sVl + rl*VSTRIDE + cw*16);
            size_t o = ((size_t)(b*NHEAD + h)*DH + d)*SEQ + s0 + cw*8;
            *reinterpret_cast<uint4*>(g_Vth + o) = vh;
            *reinterpret_cast<uint4*>(g_Vtl + o) = vl;
        }
    }
}

// ---------------------------------------------------------------------------
// Output projection (R8, unchanged)
// ---------------------------------------------------------------------------
__global__ void __launch_bounds__(256)
oproj_kernel(const float* __restrict__ bo, float* __restrict__ out)
{
    extern __shared__ char smem[];
    const int tid = threadIdx.x, wid = tid >> 5, lane = tid & 31;
    const int gid = lane >> 2, tig = lane & 3;
    const int m0 = blockIdx.y*128, n0 = blockIdx.x*128;
    const int i0w = (wid & 3)*32, j0w = (wid >> 2)*64;

    const __nv_bfloat16* Ah = g_Xh + (size_t)m0*D_MODEL;
    const __nv_bfloat16* Al = g_Xl + (size_t)m0*D_MODEL;
    const __nv_bfloat16* Bh = g_Wh + (size_t)3*N2 + (size_t)n0*D_MODEL;
    const __nv_bfloat16* Bl = g_Wl + (size_t)3*N2 + (size_t)n0*D_MODEL;

    float acc[2][8][4];
#pragma unroll
    for (int mt = 0; mt < 2; mt++)
#pragma unroll
        for (int nt = 0; nt < 8; nt++)
#pragma unroll
            for (int q = 0; q < 4; q++) acc[mt][nt][q] = 0.f;

    {
        char* buf = smem;
        cp_tile128(buf,                Ah, D_MODEL, tid);
        cp_tile128(buf +   TILE_BYTES, Al, D_MODEL, tid);
        cp_tile128(buf + 2*TILE_BYTES, Bh, D_MODEL, tid);
        cp_tile128(buf + 3*TILE_BYTES, Bl, D_MODEL, tid);
        CP_COMMIT();
    }
    for (int ch = 0; ch < 8; ch++) {
        if (ch < 7) {
            char* buf = smem + ((ch+1)&1)*(4*TILE_BYTES);
            const int k0 = (ch+1)*64;
            cp_tile128(buf,                Ah + k0, D_MODEL, tid);
            cp_tile128(buf +   TILE_BYTES, Al + k0, D_MODEL, tid);
            cp_tile128(buf + 2*TILE_BYTES, Bh + k0, D_MODEL, tid);
            cp_tile128(buf + 3*TILE_BYTES, Bl + k0, D_MODEL, tid);
            CP_COMMIT();
            asm volatile("cp.async.wait_group 1;" ::: "memory");
        } else {
            asm volatile("cp.async.wait_group 0;" ::: "memory");
        }
        __syncthreads();
        char* buf = smem + (ch&1)*(4*TILE_BYTES);
        hmma_3pass<8>(buf, buf + TILE_BYTES, buf + 2*TILE_BYTES, buf + 3*TILE_BYTES,
                      i0w, j0w, gid, tig, acc);
        __syncthreads();
    }

#pragma unroll
    for (int nt = 0; nt < 8; nt++) {
        const int col = n0 + j0w + nt*8 + tig*2;
        const float b0v = bo[col], b1v = bo[col+1];
#pragma unroll
        for (int mt = 0; mt < 2; mt++) {
#pragma unroll
            for (int half = 0; half < 2; half++) {
                const int row = m0 + i0w + mt*16 + gid + half*8;
                float2 o;
                o.x = acc[mt][nt][half*2+0] + b0v;
                o.y = acc[mt][nt][half*2+1] + b1v;
                *reinterpret_cast<float2*>(out + (size_t)row*D_MODEL + col) = o;
            }
        }
    }
}

// ---------------------------------------------------------------------------
// Score kernel (R8, unchanged): masked, scaled fp32 scores to attn.
// ---------------------------------------------------------------------------
#define SCORE_SMEM (4*TILE_BYTES)
__global__ void __launch_bounds__(256)
score_kernel(const int* __restrict__ mask, float* attn_arg)
{
    float* attn = attn_arg ? attn_arg : g_attn_fallback;
    extern __shared__ char smem[];
    char* sQ0 = smem;
    char* sQ1 = smem + TILE_BYTES;
    char* sK0 = smem + 2*TILE_BYTES;
    char* sK1 = smem + 3*TILE_BYTES;

    const int tid = threadIdx.x, wid = tid >> 5, lane = tid & 31;
    const int gid = lane >> 2, tig = lane & 3;
    const int bh = blockIdx.z, b = bh >> 3;
    const int m0 = blockIdx.y*128, n0 = blockIdx.x*128;
    const int i0w = (wid & 3)*32, j0w = (wid >> 2)*64;

    cp_tile128(sQ0, g_Qh + ((size_t)bh*SEQ + m0)*DH, DH, tid);
    cp_tile128(sQ1, g_Ql + ((size_t)bh*SEQ + m0)*DH, DH, tid);
    cp_tile128(sK0, g_Kh + ((size_t)bh*SEQ + n0)*DH, DH, tid);
    cp_tile128(sK1, g_Kl + ((size_t)bh*SEQ + n0)*DH, DH, tid);
    CP_COMMIT();
    asm volatile("cp.async.wait_group 0;" ::: "memory");
    __syncthreads();

    float acc[2][8][4];
#pragma unroll
    for (int mt = 0; mt < 2; mt++)
#pragma unroll
        for (int nt = 0; nt < 8; nt++)
#pragma unroll
            for (int q = 0; q < 4; q++) acc[mt][nt][q] = 0.f;

    hmma_3pass<8>(sQ0, sQ1, sK0, sK1, i0w, j0w, gid, tig, acc);

#pragma unroll
    for (int nt = 0; nt < 8; nt++) {
        const int col = n0 + j0w + nt*8 + tig*2;
        const int mv0 = __ldg(mask + b*SEQ + col);
        const int mv1 = __ldg(mask + b*SEQ + col + 1);
#pragma unroll
        for (int mt = 0; mt < 2; mt++) {
#pragma unroll
            for (int half = 0; half < 2; half++) {
                const int row = m0 + i0w + mt*16 + gid + half*8;
                float v0 = acc[mt][nt][half*2+0] * 0.125f;
                float v1 = acc[mt][nt][half*2+1] * 0.125f;
                if (mv0 == 0) v0 = -1.0e9f;
                if (mv1 == 0) v1 = -1.0e9f;
                float2 o; o.x = v0; o.y = v1;
                *reinterpret_cast<float2*>(attn + ((size_t)bh*SEQ + row)*SEQ + col) = o;
            }
        }
    }
}

// ---------------------------------------------------------------------------
// Softmax (R8, unchanged): normalize in place, emit bf16 hi/lo.
// ---------------------------------------------------------------------------
__global__ void __launch_bounds__(256)
softmax_kernel(float* attn_arg)
{
    float* attn = attn_arg ? attn_arg : g_attn_fallback;
    __shared__ float red[8];
    const size_t row = blockIdx.x;
    float* p = attn + row * (size_t)SEQ;
    const int tid = threadIdx.x;

    float4 v0 = reinterpret_cast<float4*>(p)[2*tid + 0];
    float4 v1 = reinterpret_cast<float4*>(p)[2*tid + 1];

    float m = fmaxf(fmaxf(fmaxf(v0.x,v0.y), fmaxf(v0.z,v0.w)),
                    fmaxf(fmaxf(v1.x,v1.y), fmaxf(v1.z,v1.w)));
#pragma unroll
    for (int o = 16; o; o >>= 1) m = fmaxf(m, __shfl_xor_sync(0xffffffffu, m, o));
    if ((tid & 31) == 0) red[tid >> 5] = m;
    __syncthreads();
    m = red[0];
#pragma unroll
    for (int w = 1; w < 8; w++) m = fmaxf(m, red[w]);
    __syncthreads();

    v0.x = __expf(v0.x - m); v0.y = __expf(v0.y - m);
    v0.z = __expf(v0.z - m); v0.w = __expf(v0.w - m);
    v1.x = __expf(v1.x - m); v1.y = __expf(v1.y - m);
    v1.z = __expf(v1.z - m); v1.w = __expf(v1.w - m);

    float s = v0.x + v0.y + v0.z + v0.w + v1.x + v1.y + v1.z + v1.w;
#pragma unroll
    for (int o = 16; o; o >>= 1) s += __shfl_xor_sync(0xffffffffu, s, o);
    if ((tid & 31) == 0) red[tid >> 5] = s;
    __syncthreads();
    s = red[0];
#pragma unroll
    for (int w = 1; w < 8; w++) s += red[w];

    const float inv = 1.0f / s;
    v0.x *= inv; v0.y *= inv; v0.z *= inv; v0.w *= inv;
    v1.x *= inv; v1.y *= inv; v1.z *= inv; v1.w *= inv;
    reinterpret_cast<float4*>(p)[2*tid + 0] = v0;
    reinterpret_cast<float4*>(p)[2*tid + 1] = v1;

    float vf[8] = { v0.x, v0.y, v0.z, v0.w, v1.x, v1.y, v1.z, v1.w };
    __nv_bfloat16 hb[8], lb[8];
#pragma unroll
    for (int e = 0; e < 8; e++) bf16_split(vf[e], hb[e], lb[e]);
    size_t off = row * (size_t)SEQ + tid*8;
    *reinterpret_cast<uint4*>(g_Ah + off) = *reinterpret_cast<uint4*>(hb);
    *reinterpret_cast<uint4*>(g_Al + off) = *reinterpret_cast<uint4*>(lb);
}

// ---------------------------------------------------------------------------
// PV kernel (R8, unchanged): A+V double-buffered cp.async, 128x64 per CTA.
// ---------------------------------------------------------------------------
#define PVBUF   (2*TILE_BYTES + 2*BTILE64)   // 55296
#define PV_SMEM (2*PVBUF)                     // 110592
__global__ void __launch_bounds__(256)
pv_kernel()
{
    extern __shared__ char smem[];
    const int tid = threadIdx.x, wid = tid >> 5, lane = tid & 31;
    const int gid = lane >> 2, tig = lane & 3;
    const int bh = blockIdx.y, b = bh >> 3, h = bh & 7;
    const int m0 = blockIdx.x * 128;
    const int i0w = (wid & 3)*32, d0w = (wid >> 2)*32;

    const __nv_bfloat16* Ah = g_Ah + ((size_t)bh*SEQ + m0)*SEQ;
    const __nv_bfloat16* Al = g_Al + ((size_t)bh*SEQ + m0)*SEQ;
    const __nv_bfloat16* Bh = g_Vth + (size_t)bh*DH*SEQ;
    const __nv_bfloat16* Bl = g_Vtl + (size_t)bh*DH*SEQ;

    float acc[2][4][4];
#pragma unroll
    for (int mt = 0; mt < 2; mt++)
#pragma unroll
        for (int nt = 0; nt < 4; nt++)
#pragma unroll
            for (int q = 0; q < 4; q++) acc[mt][nt][q] = 0.f;

    {
        char* buf = smem;
        cp_tile128(buf,                         Ah, SEQ, tid);
        cp_tile128(buf + TILE_BYTES,            Al, SEQ, tid);
        cp_tile64 (buf + 2*TILE_BYTES,           Bh, SEQ, tid);
        cp_tile64 (buf + 2*TILE_BYTES + BTILE64, Bl, SEQ, tid);
        CP_COMMIT();
    }
    for (int ch = 0; ch < 32; ch++) {
        if (ch < 31) {
            char* buf = smem + ((ch+1)&1)*PVBUF;
            const int j0 = (ch+1)*64;
            cp_tile128(buf,                         Ah + j0, SEQ, tid);
            cp_tile128(buf + TILE_BYTES,            Al + j0, SEQ, tid);
            cp_tile64 (buf + 2*TILE_BYTES,           Bh + j0, SEQ, tid);
            cp_tile64 (buf + 2*TILE_BYTES + BTILE64, Bl + j0, SEQ, tid);
            CP_COMMIT();
            asm volatile("cp.async.wait_group 1;" ::: "memory");
        } else {
            asm volatile("cp.async.wait_group 0;" ::: "memory");
        }
        __syncthreads();
        char* buf = smem + (ch&1)*PVBUF;
        hmma_3pass<4>(buf, buf + TILE_BYTES, buf + 2*TILE_BYTES, buf + 2*TILE_BYTES + BTILE64,
                      i0w, d0w, gid, tig, acc);
        __syncthreads();
    }

#pragma unroll
    for (int nt = 0; nt < 4; nt++) {
        const int d = d0w + nt*8 + tig*2;
#pragma unroll
        for (int mt = 0; mt < 2; mt++) {
#pragma unroll
            for (int half = 0; half < 2; half++) {
                const int row = m0 + i0w + mt*16 + gid + half*8;
                float v0 = acc[mt][nt][half*2+0];
                float v1 = acc[mt][nt][half*2+1];
                __nv_bfloat16 h0,l0,h1,l1;
                bf16_split(v0,h0,l0); bf16_split(v1,h1,l1);
                size_t o = ((size_t)(b*SEQ + row))*D_MODEL + h*DH + d;
                *reinterpret_cast<uint32_t*>(g_Xh + o) = pack2(h0,h1);
                *reinterpret_cast<uint32_t*>(g_Xl + o) = pack2(l0,l1);
            }
        }
    }
}

// ---------------------------------------------------------------------------
extern "C" void kernel_launch(void* const* d_in, const int* in_sizes, int n_in,
                              void* d_out, int out_size)
{
    const float* query = (const float*)d_in[0];
    const float* key   = (const float*)d_in[1];
    const float* value = (const float*)d_in[2];
    const int*   mask  = (const int*)  d_in[3];
    const float* Wq    = (const float*)d_in[4];
    const float* bq    = (const float*)d_in[5];
    const float* Wk    = (const float*)d_in[6];
    const float* bk    = (const float*)d_in[7];
    const float* Wv    = (const float*)d_in[8];
    const float* bv    = (const float*)d_in[9];
    const float* Wo    = (const float*)d_in[10];
    const float* bo    = (const float*)d_in[11];

    float* out = (float*)d_out;
    float* attn_arg = ((long long)out_size >= (long long)OUT_ELEMS + ATTN_ELEMS)
                      ? (out + OUT_ELEMS) : nullptr;

    cudaFuncSetAttribute(qkv_proj_kernel, cudaFuncAttributeMaxDynamicSharedMemorySize, PROJ_SMEM);
    cudaFuncSetAttribute(oproj_kernel,    cudaFuncAttributeMaxDynamicSharedMemorySize, PROJ_SMEM);
    cudaFuncSetAttribute(score_kernel,    cudaFuncAttributeMaxDynamicSharedMemorySize, SCORE_SMEM);
    cudaFuncSetAttribute(pv_kernel,       cudaFuncAttributeMaxDynamicSharedMemorySize, PV_SMEM);

    dim3 blk(256);
    split_kernel   <<<dim3(256, 7), blk>>>(query, key, value, Wq, Wk, Wv, Wo);
    qkv_proj_kernel<<<dim3(4, 32, 3), blk, PROJ_SMEM>>>(bq, bk, bv);
    score_kernel   <<<dim3(16, 16, 16), blk, SCORE_SMEM>>>(mask, attn_arg);
    softmax_kernel <<<dim3(NBH*SEQ), blk>>>(attn_arg);
    pv_kernel      <<<dim3(16, 16), blk, PV_SMEM>>>();
    oproj_kernel   <<<dim3(4, 32), blk, PROJ_SMEM>>>(bo, out);
}